// round 1
// baseline (speedup 1.0000x reference)
#include <cuda_runtime.h>
#include <math.h>

#define D 128
#define D4 32
#define NMAX 50000
#define EMAX 800000
#define GMAX 512
#define BN_EPS 1e-5f
#define SLOPE 0.1f
#define CH 512          // scan chunk size
#define NCMAX 128       // >= ceil(NMAX/CH) = 98
#define SROWS 256       // rows per stats block
#define SPMAX 256       // >= ceil(NMAX/SROWS) = 196

// ---------------- scratch (static device globals; no allocation) -------------
__device__ float g_buf0[NMAX * D];   // x_in / x_out per layer
__device__ float g_buf1[NMAX * D];   // h = x @ W
__device__ float g_buf2[NMAX * D];   // agg
__device__ float g_dinv[NMAX];
__device__ int   g_deg[NMAX];
__device__ int   g_rowstart[NMAX + 1];
__device__ int   g_wpos[NMAX];
__device__ int   g_srcs[EMAX];
__device__ int   g_csum[NCMAX];
__device__ int   g_coff[NCMAX];
__device__ float g_psum[SPMAX * D];
__device__ float g_psumsq[SPMAX * D];
__device__ float g_mu[D];
__device__ float g_rinv[D];
__device__ int   g_gcnt[GMAX];
__device__ int   g_gstart[GMAX + 1];
__device__ float g_pooled[GMAX * D];
__device__ float g_z1[GMAX * D];
__device__ float g_z2[GMAX * D];

// ---------------- degree / CSR construction ---------------------------------
__global__ void k_zero_deg(int N) {
    int i = blockIdx.x * blockDim.x + threadIdx.x;
    if (i < N) g_deg[i] = 0;
}

__global__ void k_count_deg(const int* __restrict__ ei, int E) {
    int e = blockIdx.x * blockDim.x + threadIdx.x;
    if (e < E) atomicAdd(&g_deg[ei[E + e]], 1);   // dst = ei[1][e]
}

__global__ void k_dinv(int N) {
    int i = blockIdx.x * blockDim.x + threadIdx.x;
    if (i < N) g_dinv[i] = rsqrtf((float)g_deg[i] + 1.0f);
}

__global__ void k_chunksum(int N) {
    __shared__ int s[CH];
    int i = blockIdx.x * CH + threadIdx.x;
    s[threadIdx.x] = (i < N) ? g_deg[i] : 0;
    __syncthreads();
    for (int off = CH / 2; off > 0; off >>= 1) {
        if (threadIdx.x < off) s[threadIdx.x] += s[threadIdx.x + off];
        __syncthreads();
    }
    if (threadIdx.x == 0) g_csum[blockIdx.x] = s[0];
}

__global__ void k_scanchunks(int NC, int N) {
    int run = 0;
    for (int i = 0; i < NC; i++) { g_coff[i] = run; run += g_csum[i]; }
    g_rowstart[N] = run;
}

__global__ void k_chunkscan(int N) {
    __shared__ int s[CH];
    int i = blockIdx.x * CH + threadIdx.x;
    int v = (i < N) ? g_deg[i] : 0;
    s[threadIdx.x] = v;
    __syncthreads();
    for (int off = 1; off < CH; off <<= 1) {
        int t = (threadIdx.x >= off) ? s[threadIdx.x - off] : 0;
        __syncthreads();
        s[threadIdx.x] += t;
        __syncthreads();
    }
    if (i < N) {
        int excl = g_coff[blockIdx.x] + s[threadIdx.x] - v;
        g_rowstart[i] = excl;
        g_wpos[i] = excl;
    }
}

__global__ void k_scatter(const int* __restrict__ ei, int E) {
    int e = blockIdx.x * blockDim.x + threadIdx.x;
    if (e < E) {
        int d = ei[E + e];
        int p = atomicAdd(&g_wpos[d], 1);
        g_srcs[p] = ei[e];
    }
}

// ---------------- graph (pooling) segment ranges -----------------------------
__global__ void k_zero_gcnt() {
    int i = blockIdx.x * blockDim.x + threadIdx.x;
    if (i < GMAX) g_gcnt[i] = 0;
}

__global__ void k_count_g(const int* __restrict__ batch, int N) {
    int i = blockIdx.x * blockDim.x + threadIdx.x;
    if (i < N) atomicAdd(&g_gcnt[batch[i]], 1);
}

__global__ void k_scan_g(int G) {
    int run = 0;
    for (int i = 0; i < G; i++) { g_gstart[i] = run; run += g_gcnt[i]; }
    g_gstart[G] = run;
}

// ---------------- GEMM: C[M,128] = A[M,128] @ B[128,128] (+bias) -------------
__global__ void k_gemm(const float* __restrict__ A, const float* __restrict__ B,
                       const float* __restrict__ bias, float* __restrict__ C,
                       int M, int addbias) {
    __shared__ float As[128][33];
    __shared__ float Bs[32][128];
    const int tid = threadIdx.x;            // 256 threads
    const int tx = tid & 15;
    const int ty = tid >> 4;
    const int row0 = blockIdx.x * 128;

    float acc[8][8];
#pragma unroll
    for (int i = 0; i < 8; i++)
#pragma unroll
        for (int j = 0; j < 8; j++) acc[i][j] = 0.0f;

    for (int k0 = 0; k0 < 128; k0 += 32) {
        // load A tile 128x32 (1024 float4, 4 per thread)
#pragma unroll
        for (int i = 0; i < 4; i++) {
            int e = tid + i * 256;
            int r = e >> 3;
            int c = (e & 7) * 4;
            float4 v = make_float4(0.f, 0.f, 0.f, 0.f);
            if (row0 + r < M)
                v = *(const float4*)&A[(size_t)(row0 + r) * 128 + k0 + c];
            As[r][c] = v.x; As[r][c + 1] = v.y; As[r][c + 2] = v.z; As[r][c + 3] = v.w;
        }
        // load B tile 32x128
#pragma unroll
        for (int i = 0; i < 4; i++) {
            int e = tid + i * 256;
            int r = e >> 5;
            int c = (e & 31) * 4;
            float4 v = *(const float4*)&B[(size_t)(k0 + r) * 128 + c];
            *(float4*)&Bs[r][c] = v;
        }
        __syncthreads();
#pragma unroll
        for (int k = 0; k < 32; k++) {
            float a[8], b[8];
#pragma unroll
            for (int ii = 0; ii < 4; ii++) {
                a[ii]     = As[ty * 4 + ii][k];
                a[4 + ii] = As[64 + ty * 4 + ii][k];
            }
            float4 b0 = *(const float4*)&Bs[k][tx * 4];
            float4 b1 = *(const float4*)&Bs[k][64 + tx * 4];
            b[0] = b0.x; b[1] = b0.y; b[2] = b0.z; b[3] = b0.w;
            b[4] = b1.x; b[5] = b1.y; b[6] = b1.z; b[7] = b1.w;
#pragma unroll
            for (int ii = 0; ii < 8; ii++)
#pragma unroll
                for (int jj = 0; jj < 8; jj++)
                    acc[ii][jj] += a[ii] * b[jj];
        }
        __syncthreads();
    }

#pragma unroll
    for (int ii = 0; ii < 8; ii++) {
        int r = row0 + ((ii < 4) ? (ty * 4 + ii) : (64 + ty * 4 + (ii - 4)));
        if (r < M) {
#pragma unroll
            for (int jg = 0; jg < 2; jg++) {
                int c0 = jg * 64 + tx * 4;
                float4 o;
                o.x = acc[ii][jg * 4 + 0];
                o.y = acc[ii][jg * 4 + 1];
                o.z = acc[ii][jg * 4 + 2];
                o.w = acc[ii][jg * 4 + 3];
                if (addbias) {
                    o.x += bias[c0];     o.y += bias[c0 + 1];
                    o.z += bias[c0 + 2]; o.w += bias[c0 + 3];
                }
                *(float4*)&C[(size_t)r * 128 + c0] = o;
            }
        }
    }
}

// ---------------- edge aggregation: warp per destination node ----------------
__global__ void k_aggregate(const float* __restrict__ h, const float* __restrict__ bias,
                            float* __restrict__ agg, int N) {
    int warp = (blockIdx.x * blockDim.x + threadIdx.x) >> 5;
    int lane = threadIdx.x & 31;
    if (warp >= N) return;
    const float4* h4 = (const float4*)h;
    float di = g_dinv[warp];
    float4 a = h4[(size_t)warp * 32 + lane];
    float sc = di * di;
    float4 acc;
    acc.x = a.x * sc; acc.y = a.y * sc; acc.z = a.z * sc; acc.w = a.w * sc;
    int s0 = g_rowstart[warp], s1 = g_rowstart[warp + 1];
    for (int j = s0; j < s1; j++) {
        int s = g_srcs[j];
        float c = g_dinv[s] * di;
        float4 v = h4[(size_t)s * 32 + lane];
        acc.x += v.x * c; acc.y += v.y * c; acc.z += v.z * c; acc.w += v.w * c;
    }
    float4 b = ((const float4*)bias)[lane];
    acc.x += b.x; acc.y += b.y; acc.z += b.z; acc.w += b.w;
    ((float4*)agg)[(size_t)warp * 32 + lane] = acc;
}

// ---------------- BatchNorm over nodes (column stats) ------------------------
__global__ void k_stats_partial(const float* __restrict__ X, int N) {
    int c = threadIdx.x;    // 128 threads
    int r0 = blockIdx.x * SROWS;
    int r1 = min(N, r0 + SROWS);
    float s = 0.f, s2 = 0.f;
    for (int r = r0; r < r1; r++) {
        float v = X[(size_t)r * 128 + c];
        s += v; s2 += v * v;
    }
    g_psum[blockIdx.x * 128 + c] = s;
    g_psumsq[blockIdx.x * 128 + c] = s2;
}

__global__ void k_stats_final(int P, int N) {
    int c = threadIdx.x;
    float s = 0.f, s2 = 0.f;
    for (int p = 0; p < P; p++) {
        s += g_psum[p * 128 + c];
        s2 += g_psumsq[p * 128 + c];
    }
    float mu = s / (float)N;
    float var = s2 / (float)N - mu * mu;
    g_mu[c] = mu;
    g_rinv[c] = rsqrtf(var + BN_EPS);
}

__global__ void k_norm(const float* __restrict__ X, const float* __restrict__ g,
                       const float* __restrict__ be, float* __restrict__ Y, int N) {
    int i = blockIdx.x * blockDim.x + threadIdx.x;  // over N*32 float4
    if (i >= N * 32) return;
    int c = (i & 31) * 4;
    float4 v = ((const float4*)X)[i];
    float4 o;
    o.x = (v.x - g_mu[c])     * g_rinv[c]     * g[c]     + be[c];
    o.y = (v.y - g_mu[c + 1]) * g_rinv[c + 1] * g[c + 1] + be[c + 1];
    o.z = (v.z - g_mu[c + 2]) * g_rinv[c + 2] * g[c + 2] + be[c + 2];
    o.w = (v.w - g_mu[c + 3]) * g_rinv[c + 3] * g[c + 3] + be[c + 3];
    o.x = o.x > 0.f ? o.x : SLOPE * o.x;
    o.y = o.y > 0.f ? o.y : SLOPE * o.y;
    o.z = o.z > 0.f ? o.z : SLOPE * o.z;
    o.w = o.w > 0.f ? o.w : SLOPE * o.w;
    ((float4*)Y)[i] = o;
}

// ---------------- mean pool (batch is sorted -> contiguous ranges) -----------
__global__ void k_pool(const float* __restrict__ h, int G) {
    int warp = (blockIdx.x * blockDim.x + threadIdx.x) >> 5;
    int lane = threadIdx.x & 31;
    if (warp >= G) return;
    const float4* h4 = (const float4*)h;
    int s0 = g_gstart[warp], s1 = g_gstart[warp + 1];
    float4 acc = make_float4(0.f, 0.f, 0.f, 0.f);
    for (int r = s0; r < s1; r++) {
        float4 v = h4[(size_t)r * 32 + lane];
        acc.x += v.x; acc.y += v.y; acc.z += v.z; acc.w += v.w;
    }
    int cnt = s1 - s0;
    float inv = 1.0f / (float)(cnt > 0 ? cnt : 1);
    acc.x *= inv; acc.y *= inv; acc.z *= inv; acc.w *= inv;
    ((float4*)g_pooled)[(size_t)warp * 32 + lane] = acc;
}

// ---------------- small BN + leaky over G rows -------------------------------
__global__ void k_bn_small(const float* __restrict__ z, const float* __restrict__ g4,
                           const float* __restrict__ be4, float* __restrict__ out, int G) {
    int c = threadIdx.x;   // 128 threads, 1 block
    float s = 0.f, s2 = 0.f;
    for (int r = 0; r < G; r++) {
        float v = z[(size_t)r * 128 + c];
        s += v; s2 += v * v;
    }
    float mu = s / (float)G;
    float var = s2 / (float)G - mu * mu;
    float rinv = rsqrtf(var + BN_EPS);
    float gg = g4[c], bb = be4[c];
    for (int r = 0; r < G; r++) {
        float v = z[(size_t)r * 128 + c];
        float t = (v - mu) * rinv * gg + bb;
        out[(size_t)r * 128 + c] = t > 0.f ? t : SLOPE * t;
    }
}

// ---------------- driver ------------------------------------------------------
extern "C" void kernel_launch(void* const* d_in, const int* in_sizes, int n_in,
                              void* d_out, int out_size) {
    const float* x      = (const float*)d_in[0];
    const int*   ei     = (const int*)d_in[1];
    const int*   batch  = (const int*)d_in[2];
    // d_in[3] = n_graphs scalar, unused (derived from out_size)
    const float* W1  = (const float*)d_in[4];
    const float* b1  = (const float*)d_in[5];
    const float* g1  = (const float*)d_in[6];
    const float* be1 = (const float*)d_in[7];
    const float* W2  = (const float*)d_in[8];
    const float* b2  = (const float*)d_in[9];
    const float* g2  = (const float*)d_in[10];
    const float* be2 = (const float*)d_in[11];
    const float* W3  = (const float*)d_in[12];
    const float* b3  = (const float*)d_in[13];
    const float* g3  = (const float*)d_in[14];
    const float* be3 = (const float*)d_in[15];
    const float* Wf1 = (const float*)d_in[16];
    const float* bf1 = (const float*)d_in[17];
    const float* g4  = (const float*)d_in[18];
    const float* be4 = (const float*)d_in[19];
    const float* Wf2 = (const float*)d_in[20];
    const float* bf2 = (const float*)d_in[21];

    int N = in_sizes[0] / D;
    int E = in_sizes[1] / 2;
    int G = out_size / D;
    if (N > NMAX || E > EMAX || G > GMAX) return;

    float *buf0, *buf1, *buf2, *pooled, *z1, *z2;
    cudaGetSymbolAddress((void**)&buf0, g_buf0);
    cudaGetSymbolAddress((void**)&buf1, g_buf1);
    cudaGetSymbolAddress((void**)&buf2, g_buf2);
    cudaGetSymbolAddress((void**)&pooled, g_pooled);
    cudaGetSymbolAddress((void**)&z1, g_z1);
    cudaGetSymbolAddress((void**)&z2, g_z2);

    int NC = (N + CH - 1) / CH;
    int P  = (N + SROWS - 1) / SROWS;

    // CSR build (per call; deterministic work)
    k_zero_deg<<<(N + 255) / 256, 256>>>(N);
    k_count_deg<<<(E + 255) / 256, 256>>>(ei, E);
    k_dinv<<<(N + 255) / 256, 256>>>(N);
    k_chunksum<<<NC, CH>>>(N);
    k_scanchunks<<<1, 1>>>(NC, N);
    k_chunkscan<<<NC, CH>>>(N);
    k_scatter<<<(E + 255) / 256, 256>>>(ei, E);

    // graph segment ranges
    k_zero_gcnt<<<(GMAX + 255) / 256, 256>>>();
    k_count_g<<<(N + 255) / 256, 256>>>(batch, N);
    k_scan_g<<<1, 1>>>(G);

    const float* Ws[3]  = {W1, W2, W3};
    const float* bs[3]  = {b1, b2, b3};
    const float* gs[3]  = {g1, g2, g3};
    const float* bes[3] = {be1, be2, be3};

    int gemm_blocks = (N + 127) / 128;
    int agg_blocks  = (N + 7) / 8;          // 8 warps per block of 256
    int norm_blocks = (N * 32 + 255) / 256;

    const float* xin = x;
    for (int L = 0; L < 3; L++) {
        k_gemm<<<gemm_blocks, 256>>>(xin, Ws[L], nullptr, buf1, N, 0);
        k_aggregate<<<agg_blocks, 256>>>(buf1, bs[L], buf2, N);
        k_stats_partial<<<P, 128>>>(buf2, N);
        k_stats_final<<<1, 128>>>(P, N);
        k_norm<<<norm_blocks, 256>>>(buf2, gs[L], bes[L], buf0, N);
        xin = buf0;
    }

    // pool + final MLP
    k_pool<<<(G + 7) / 8, 256>>>(buf0, G);
    int gemm_blocks_g = (G + 127) / 128;
    k_gemm<<<gemm_blocks_g, 256>>>(pooled, Wf1, bf1, z1, G, 1);
    k_bn_small<<<1, 128>>>(z1, g4, be4, z2, G);
    k_gemm<<<gemm_blocks_g, 256>>>(z2, Wf2, bf2, (float*)d_out, G, 1);
}

// round 3
// speedup vs baseline: 1.0741x; 1.0741x over previous
#include <cuda_runtime.h>
#include <math.h>
#include <stdint.h>

#define D 128
#define NMAX 50000
#define EMAX 800000
#define GMAX 512
#define BN_EPS 1e-5f
#define SLOPE 0.1f
#define CH 512
#define NCMAX 128
#define SROWS 256
#define SPMAX 256

// ---------------- scratch (static device globals; no allocation) -------------
__device__ float g_buf0[NMAX * D];
__device__ float g_buf1[NMAX * D];
__device__ float g_buf2[NMAX * D];
__device__ float g_WT[3][D * D];
__device__ float g_dinv[NMAX];
__device__ int   g_deg[NMAX];
__device__ int   g_rowstart[NMAX + 1];
__device__ int   g_wpos[NMAX];
__device__ int   g_srcs[EMAX];
__device__ int   g_csum[NCMAX];
__device__ int   g_coff[NCMAX];
__device__ float g_psum[SPMAX * D];
__device__ float g_psumsq[SPMAX * D];
__device__ float g_scale[D];
__device__ float g_shift[D];
__device__ int   g_gcnt[GMAX];
__device__ int   g_gstart[GMAX + 1];
__device__ float g_pooled[GMAX * D];
__device__ float g_z1[GMAX * D];
__device__ float g_z2[GMAX * D];

// ---------------- tf32 split helper ------------------------------------------
__device__ __forceinline__ void tf32_split(float v, float& hi, float& lo) {
    uint32_t t;
    asm("cvt.rna.tf32.f32 %0, %1;" : "=r"(t) : "f"(v));
    hi = __uint_as_float(t);
    float r = v - hi;
    asm("cvt.rna.tf32.f32 %0, %1;" : "=r"(t) : "f"(r));
    lo = __uint_as_float(t);
}

__device__ __forceinline__ void mma_tf32(float* d, uint32_t a0, uint32_t a1,
                                         uint32_t a2, uint32_t a3,
                                         uint32_t b0, uint32_t b1) {
    asm volatile(
        "mma.sync.aligned.m16n8k8.row.col.f32.tf32.tf32.f32 "
        "{%0,%1,%2,%3}, {%4,%5,%6,%7}, {%8,%9}, {%0,%1,%2,%3};"
        : "+f"(d[0]), "+f"(d[1]), "+f"(d[2]), "+f"(d[3])
        : "r"(a0), "r"(a1), "r"(a2), "r"(a3), "r"(b0), "r"(b1));
}

// ---------------- mma.sync tf32 3-term split GEMM ----------------------------
// C[M,128] = leaky(norm(A))[M,128] @ W[128,128]  (WT[n][k] = W[k][n])
#define KC 32
#define AST 36      // smem row stride (floats): 32 + 4 pad -> conflict-free frags
#define GEMM_SMEM (4 * 128 * AST * 4)   // sAh, sAl, sBh, sBl = 73728 B

__global__ void __launch_bounds__(256, 2)
k_gemm_mma(const float* __restrict__ A, const float* __restrict__ WT,
           float* __restrict__ C, int M, int apply_norm) {
    extern __shared__ float sm[];
    float* sAh = sm;
    float* sAl = sm + 128 * AST;
    float* sBh = sm + 2 * 128 * AST;
    float* sBl = sm + 3 * 128 * AST;

    const int tid = threadIdx.x;
    const int wid = tid >> 5;
    const int lid = tid & 31;
    const int g   = lid >> 2;       // 0..7
    const int tg  = lid & 3;        // 0..3
    const int wm  = wid & 1;        // 2 warp-rows (64 rows each)
    const int wn  = wid >> 1;       // 4 warp-cols (32 cols each)
    const int row0 = blockIdx.x * 128;

    float acc[4][4][4];
#pragma unroll
    for (int mt = 0; mt < 4; mt++)
#pragma unroll
        for (int nt = 0; nt < 4; nt++)
#pragma unroll
            for (int i = 0; i < 4; i++) acc[mt][nt][i] = 0.0f;

    for (int p = 0; p < 4; p++) {
        if (p) __syncthreads();
        // load + split A chunk [128 x 32]
#pragma unroll
        for (int i = 0; i < 4; i++) {
            int idx = tid + i * 256;
            int r = idx >> 3;
            int c = (idx & 7) * 4;
            float4 v = make_float4(0.f, 0.f, 0.f, 0.f);
            if (row0 + r < M)
                v = *(const float4*)&A[(size_t)(row0 + r) * 128 + p * 32 + c];
            if (apply_norm) {
                int cg = p * 32 + c;
                v.x = v.x * g_scale[cg]     + g_shift[cg];
                v.y = v.y * g_scale[cg + 1] + g_shift[cg + 1];
                v.z = v.z * g_scale[cg + 2] + g_shift[cg + 2];
                v.w = v.w * g_scale[cg + 3] + g_shift[cg + 3];
                v.x = v.x > 0.f ? v.x : SLOPE * v.x;
                v.y = v.y > 0.f ? v.y : SLOPE * v.y;
                v.z = v.z > 0.f ? v.z : SLOPE * v.z;
                v.w = v.w > 0.f ? v.w : SLOPE * v.w;
            }
            float4 hi, lo;
            tf32_split(v.x, hi.x, lo.x);
            tf32_split(v.y, hi.y, lo.y);
            tf32_split(v.z, hi.z, lo.z);
            tf32_split(v.w, hi.w, lo.w);
            *(float4*)&sAh[r * AST + c] = hi;
            *(float4*)&sAl[r * AST + c] = lo;
        }
        // load + split B chunk (WT rows n=0..127, k-cols of this chunk)
#pragma unroll
        for (int i = 0; i < 4; i++) {
            int idx = tid + i * 256;
            int r = idx >> 3;
            int c = (idx & 7) * 4;
            float4 v = *(const float4*)&WT[(size_t)r * 128 + p * 32 + c];
            float4 hi, lo;
            tf32_split(v.x, hi.x, lo.x);
            tf32_split(v.y, hi.y, lo.y);
            tf32_split(v.z, hi.z, lo.z);
            tf32_split(v.w, hi.w, lo.w);
            *(float4*)&sBh[r * AST + c] = hi;
            *(float4*)&sBl[r * AST + c] = lo;
        }
        __syncthreads();

#pragma unroll
        for (int t = 0; t < 3; t++) {
            const float* As = (t == 2) ? sAl : sAh;
            const float* Bs = (t == 1) ? sBl : sBh;
#pragma unroll
            for (int k8 = 0; k8 < 4; k8++) {
                int k0 = k8 * 8;
                uint32_t af[4][4];
#pragma unroll
                for (int mt = 0; mt < 4; mt++) {
                    int r0 = wm * 64 + mt * 16 + g;
                    af[mt][0] = __float_as_uint(As[r0 * AST + k0 + tg]);
                    af[mt][1] = __float_as_uint(As[(r0 + 8) * AST + k0 + tg]);
                    af[mt][2] = __float_as_uint(As[r0 * AST + k0 + tg + 4]);
                    af[mt][3] = __float_as_uint(As[(r0 + 8) * AST + k0 + tg + 4]);
                }
                uint32_t bf[4][2];
#pragma unroll
                for (int nt = 0; nt < 4; nt++) {
                    int c0 = wn * 32 + nt * 8 + g;
                    bf[nt][0] = __float_as_uint(Bs[c0 * AST + k0 + tg]);
                    bf[nt][1] = __float_as_uint(Bs[c0 * AST + k0 + tg + 4]);
                }
#pragma unroll
                for (int mt = 0; mt < 4; mt++)
#pragma unroll
                    for (int nt = 0; nt < 4; nt++)
                        mma_tf32(acc[mt][nt], af[mt][0], af[mt][1], af[mt][2],
                                 af[mt][3], bf[nt][0], bf[nt][1]);
            }
        }
    }
    __syncthreads();

    // stage through smem for coalesced stores (reuse tile memory: 128x129 floats)
    float* sOut = sm;
#pragma unroll
    for (int mt = 0; mt < 4; mt++) {
        int r0 = wm * 64 + mt * 16 + g;
#pragma unroll
        for (int nt = 0; nt < 4; nt++) {
            int c0 = wn * 32 + nt * 8 + tg * 2;
            sOut[r0 * 129 + c0]           = acc[mt][nt][0];
            sOut[r0 * 129 + c0 + 1]       = acc[mt][nt][1];
            sOut[(r0 + 8) * 129 + c0]     = acc[mt][nt][2];
            sOut[(r0 + 8) * 129 + c0 + 1] = acc[mt][nt][3];
        }
    }
    __syncthreads();

#pragma unroll 4
    for (int i = 0; i < 64; i++) {
        int idx = tid + i * 256;
        int r = idx >> 7;
        int c = idx & 127;
        if (row0 + r < M)
            C[(size_t)(row0 + r) * 128 + c] = sOut[r * 129 + c];
    }
}

// ---------------- weight transpose (tiled) -----------------------------------
__global__ void k_transpose(const float* __restrict__ W, float* __restrict__ WT) {
    __shared__ float t[32][33];
    int bx = blockIdx.x, by = blockIdx.y;
    int tx = threadIdx.x, ty = threadIdx.y;
#pragma unroll
    for (int i = 0; i < 32; i += 8)
        t[ty + i][tx] = W[(by * 32 + ty + i) * 128 + bx * 32 + tx];
    __syncthreads();
#pragma unroll
    for (int i = 0; i < 32; i += 8)
        WT[(bx * 32 + ty + i) * 128 + by * 32 + tx] = t[tx][ty + i];
}

// ---------------- degree / CSR construction ---------------------------------
__global__ void k_zero_deg(int N) {
    int i = blockIdx.x * blockDim.x + threadIdx.x;
    if (i < N) g_deg[i] = 0;
}
__global__ void k_count_deg(const int* __restrict__ ei, int E) {
    int e = blockIdx.x * blockDim.x + threadIdx.x;
    if (e < E) atomicAdd(&g_deg[ei[E + e]], 1);
}
__global__ void k_dinv(int N) {
    int i = blockIdx.x * blockDim.x + threadIdx.x;
    if (i < N) g_dinv[i] = rsqrtf((float)g_deg[i] + 1.0f);
}
__global__ void k_chunksum(int N) {
    __shared__ int s[CH];
    int i = blockIdx.x * CH + threadIdx.x;
    s[threadIdx.x] = (i < N) ? g_deg[i] : 0;
    __syncthreads();
    for (int off = CH / 2; off > 0; off >>= 1) {
        if (threadIdx.x < off) s[threadIdx.x] += s[threadIdx.x + off];
        __syncthreads();
    }
    if (threadIdx.x == 0) g_csum[blockIdx.x] = s[0];
}
__global__ void k_scanchunks(int NC, int N) {
    int run = 0;
    for (int i = 0; i < NC; i++) { g_coff[i] = run; run += g_csum[i]; }
    g_rowstart[N] = run;
}
__global__ void k_chunkscan(int N) {
    __shared__ int s[CH];
    int i = blockIdx.x * CH + threadIdx.x;
    int v = (i < N) ? g_deg[i] : 0;
    s[threadIdx.x] = v;
    __syncthreads();
    for (int off = 1; off < CH; off <<= 1) {
        int t = (threadIdx.x >= off) ? s[threadIdx.x - off] : 0;
        __syncthreads();
        s[threadIdx.x] += t;
        __syncthreads();
    }
    if (i < N) {
        int excl = g_coff[blockIdx.x] + s[threadIdx.x] - v;
        g_rowstart[i] = excl;
        g_wpos[i] = excl;
    }
}
__global__ void k_scatter(const int* __restrict__ ei, int E) {
    int e = blockIdx.x * blockDim.x + threadIdx.x;
    if (e < E) {
        int d = ei[E + e];
        int p = atomicAdd(&g_wpos[d], 1);
        g_srcs[p] = ei[e];
    }
}

// ---------------- graph (pooling) segment ranges -----------------------------
__global__ void k_zero_gcnt() {
    int i = blockIdx.x * blockDim.x + threadIdx.x;
    if (i < GMAX) g_gcnt[i] = 0;
}
__global__ void k_count_g(const int* __restrict__ batch, int N) {
    int i = blockIdx.x * blockDim.x + threadIdx.x;
    if (i < N) atomicAdd(&g_gcnt[batch[i]], 1);
}
__global__ void k_scan_g(int G) {
    int run = 0;
    for (int i = 0; i < G; i++) { g_gstart[i] = run; run += g_gcnt[i]; }
    g_gstart[G] = run;
}

// ---------------- SIMT GEMM (small FC layers) --------------------------------
__global__ void k_gemm(const float* __restrict__ A, const float* __restrict__ B,
                       const float* __restrict__ bias, float* __restrict__ C,
                       int M, int addbias) {
    __shared__ float As[128][33];
    __shared__ float Bs[32][128];
    const int tid = threadIdx.x;
    const int tx = tid & 15;
    const int ty = tid >> 4;
    const int row0 = blockIdx.x * 128;

    float acc[8][8];
#pragma unroll
    for (int i = 0; i < 8; i++)
#pragma unroll
        for (int j = 0; j < 8; j++) acc[i][j] = 0.0f;

    for (int k0 = 0; k0 < 128; k0 += 32) {
#pragma unroll
        for (int i = 0; i < 4; i++) {
            int e = tid + i * 256;
            int r = e >> 3;
            int c = (e & 7) * 4;
            float4 v = make_float4(0.f, 0.f, 0.f, 0.f);
            if (row0 + r < M)
                v = *(const float4*)&A[(size_t)(row0 + r) * 128 + k0 + c];
            As[r][c] = v.x; As[r][c + 1] = v.y; As[r][c + 2] = v.z; As[r][c + 3] = v.w;
        }
#pragma unroll
        for (int i = 0; i < 4; i++) {
            int e = tid + i * 256;
            int r = e >> 5;
            int c = (e & 31) * 4;
            float4 v = *(const float4*)&B[(size_t)(k0 + r) * 128 + c];
            *(float4*)&Bs[r][c] = v;
        }
        __syncthreads();
#pragma unroll
        for (int k = 0; k < 32; k++) {
            float a[8], b[8];
#pragma unroll
            for (int ii = 0; ii < 4; ii++) {
                a[ii]     = As[ty * 4 + ii][k];
                a[4 + ii] = As[64 + ty * 4 + ii][k];
            }
            float4 b0 = *(const float4*)&Bs[k][tx * 4];
            float4 b1 = *(const float4*)&Bs[k][64 + tx * 4];
            b[0] = b0.x; b[1] = b0.y; b[2] = b0.z; b[3] = b0.w;
            b[4] = b1.x; b[5] = b1.y; b[6] = b1.z; b[7] = b1.w;
#pragma unroll
            for (int ii = 0; ii < 8; ii++)
#pragma unroll
                for (int jj = 0; jj < 8; jj++)
                    acc[ii][jj] += a[ii] * b[jj];
        }
        __syncthreads();
    }

#pragma unroll
    for (int ii = 0; ii < 8; ii++) {
        int r = row0 + ((ii < 4) ? (ty * 4 + ii) : (64 + ty * 4 + (ii - 4)));
        if (r < M) {
#pragma unroll
            for (int jg = 0; jg < 2; jg++) {
                int c0 = jg * 64 + tx * 4;
                float4 o;
                o.x = acc[ii][jg * 4 + 0];
                o.y = acc[ii][jg * 4 + 1];
                o.z = acc[ii][jg * 4 + 2];
                o.w = acc[ii][jg * 4 + 3];
                if (addbias) {
                    o.x += bias[c0];     o.y += bias[c0 + 1];
                    o.z += bias[c0 + 2]; o.w += bias[c0 + 3];
                }
                *(float4*)&C[(size_t)r * 128 + c0] = o;
            }
        }
    }
}

// ---------------- edge aggregation: warp per destination node ----------------
__global__ void k_aggregate(const float* __restrict__ h, const float* __restrict__ bias,
                            float* __restrict__ agg, int N) {
    int warp = (blockIdx.x * blockDim.x + threadIdx.x) >> 5;
    int lane = threadIdx.x & 31;
    if (warp >= N) return;
    const float4* h4 = (const float4*)h;
    float di = g_dinv[warp];
    float4 a = h4[(size_t)warp * 32 + lane];
    float sc = di * di;
    float4 acc;
    acc.x = a.x * sc; acc.y = a.y * sc; acc.z = a.z * sc; acc.w = a.w * sc;
    int s0 = g_rowstart[warp], s1 = g_rowstart[warp + 1];
    for (int j = s0; j < s1; j++) {
        int s = g_srcs[j];
        float c = g_dinv[s] * di;
        float4 v = h4[(size_t)s * 32 + lane];
        acc.x += v.x * c; acc.y += v.y * c; acc.z += v.z * c; acc.w += v.w * c;
    }
    float4 b = ((const float4*)bias)[lane];
    acc.x += b.x; acc.y += b.y; acc.z += b.z; acc.w += b.w;
    ((float4*)agg)[(size_t)warp * 32 + lane] = acc;
}

// ---------------- BatchNorm stats --------------------------------------------
__global__ void k_stats_partial(const float* __restrict__ X, int N) {
    int c = threadIdx.x;
    int r0 = blockIdx.x * SROWS;
    int r1 = min(N, r0 + SROWS);
    float s = 0.f, s2 = 0.f;
    for (int r = r0; r < r1; r++) {
        float v = X[(size_t)r * 128 + c];
        s += v; s2 += v * v;
    }
    g_psum[blockIdx.x * 128 + c] = s;
    g_psumsq[blockIdx.x * 128 + c] = s2;
}
__global__ void k_stats_final(int P, int N, const float* __restrict__ g,
                              const float* __restrict__ be) {
    int c = threadIdx.x;
    float s = 0.f, s2 = 0.f;
    for (int p = 0; p < P; p++) {
        s += g_psum[p * 128 + c];
        s2 += g_psumsq[p * 128 + c];
    }
    float mu = s / (float)N;
    float var = s2 / (float)N - mu * mu;
    float rinv = rsqrtf(var + BN_EPS);
    float sc = rinv * g[c];
    g_scale[c] = sc;
    g_shift[c] = be[c] - mu * sc;
}

__global__ void k_norm(const float* __restrict__ X, float* __restrict__ Y, int N) {
    int i = blockIdx.x * blockDim.x + threadIdx.x;
    if (i >= N * 32) return;
    int c = (i & 31) * 4;
    float4 v = ((const float4*)X)[i];
    float4 o;
    o.x = v.x * g_scale[c]     + g_shift[c];
    o.y = v.y * g_scale[c + 1] + g_shift[c + 1];
    o.z = v.z * g_scale[c + 2] + g_shift[c + 2];
    o.w = v.w * g_scale[c + 3] + g_shift[c + 3];
    o.x = o.x > 0.f ? o.x : SLOPE * o.x;
    o.y = o.y > 0.f ? o.y : SLOPE * o.y;
    o.z = o.z > 0.f ? o.z : SLOPE * o.z;
    o.w = o.w > 0.f ? o.w : SLOPE * o.w;
    ((float4*)Y)[i] = o;
}

// ---------------- mean pool ---------------------------------------------------
__global__ void k_pool(const float* __restrict__ h, int G) {
    int warp = (blockIdx.x * blockDim.x + threadIdx.x) >> 5;
    int lane = threadIdx.x & 31;
    if (warp >= G) return;
    const float4* h4 = (const float4*)h;
    int s0 = g_gstart[warp], s1 = g_gstart[warp + 1];
    float4 acc = make_float4(0.f, 0.f, 0.f, 0.f);
    for (int r = s0; r < s1; r++) {
        float4 v = h4[(size_t)r * 32 + lane];
        acc.x += v.x; acc.y += v.y; acc.z += v.z; acc.w += v.w;
    }
    int cnt = s1 - s0;
    float inv = 1.0f / (float)(cnt > 0 ? cnt : 1);
    acc.x *= inv; acc.y *= inv; acc.z *= inv; acc.w *= inv;
    ((float4*)g_pooled)[(size_t)warp * 32 + lane] = acc;
}

// ---------------- small BN + leaky over G rows -------------------------------
__global__ void k_bn_small(const float* __restrict__ z, const float* __restrict__ g4,
                           const float* __restrict__ be4, float* __restrict__ out, int G) {
    int c = threadIdx.x;
    float s = 0.f, s2 = 0.f;
    for (int r = 0; r < G; r++) {
        float v = z[(size_t)r * 128 + c];
        s += v; s2 += v * v;
    }
    float mu = s / (float)G;
    float var = s2 / (float)G - mu * mu;
    float rinv = rsqrtf(var + BN_EPS);
    float gg = g4[c], bb = be4[c];
    for (int r = 0; r < G; r++) {
        float v = z[(size_t)r * 128 + c];
        float t = (v - mu) * rinv * gg + bb;
        out[(size_t)r * 128 + c] = t > 0.f ? t : SLOPE * t;
    }
}

// ---------------- driver ------------------------------------------------------
extern "C" void kernel_launch(void* const* d_in, const int* in_sizes, int n_in,
                              void* d_out, int out_size) {
    const float* x      = (const float*)d_in[0];
    const int*   ei     = (const int*)d_in[1];
    const int*   batch  = (const int*)d_in[2];
    const float* W1  = (const float*)d_in[4];
    const float* b1  = (const float*)d_in[5];
    const float* g1  = (const float*)d_in[6];
    const float* be1 = (const float*)d_in[7];
    const float* W2  = (const float*)d_in[8];
    const float* b2  = (const float*)d_in[9];
    const float* g2  = (const float*)d_in[10];
    const float* be2 = (const float*)d_in[11];
    const float* W3  = (const float*)d_in[12];
    const float* b3  = (const float*)d_in[13];
    const float* g3  = (const float*)d_in[14];
    const float* be3 = (const float*)d_in[15];
    const float* Wf1 = (const float*)d_in[16];
    const float* bf1 = (const float*)d_in[17];
    const float* g4  = (const float*)d_in[18];
    const float* be4 = (const float*)d_in[19];
    const float* Wf2 = (const float*)d_in[20];
    const float* bf2 = (const float*)d_in[21];

    int N = in_sizes[0] / D;
    int E = in_sizes[1] / 2;
    int G = out_size / D;
    if (N > NMAX || E > EMAX || G > GMAX) return;

    cudaFuncSetAttribute(k_gemm_mma, cudaFuncAttributeMaxDynamicSharedMemorySize, GEMM_SMEM);

    float *buf0, *buf1, *buf2, *pooled, *z1, *z2, *wt;
    cudaGetSymbolAddress((void**)&buf0, g_buf0);
    cudaGetSymbolAddress((void**)&buf1, g_buf1);
    cudaGetSymbolAddress((void**)&buf2, g_buf2);
    cudaGetSymbolAddress((void**)&pooled, g_pooled);
    cudaGetSymbolAddress((void**)&z1, g_z1);
    cudaGetSymbolAddress((void**)&z2, g_z2);
    cudaGetSymbolAddress((void**)&wt, g_WT);
    float* wt0 = wt;
    float* wt1 = wt + D * D;
    float* wt2 = wt + 2 * D * D;

    int NC = (N + CH - 1) / CH;
    int P  = (N + SROWS - 1) / SROWS;

    // weight transposes
    k_transpose<<<dim3(4, 4), dim3(32, 8)>>>(W1, wt0);
    k_transpose<<<dim3(4, 4), dim3(32, 8)>>>(W2, wt1);
    k_transpose<<<dim3(4, 4), dim3(32, 8)>>>(W3, wt2);

    // CSR build
    k_zero_deg<<<(N + 255) / 256, 256>>>(N);
    k_count_deg<<<(E + 255) / 256, 256>>>(ei, E);
    k_dinv<<<(N + 255) / 256, 256>>>(N);
    k_chunksum<<<NC, CH>>>(N);
    k_scanchunks<<<1, 1>>>(NC, N);
    k_chunkscan<<<NC, CH>>>(N);
    k_scatter<<<(E + 255) / 256, 256>>>(ei, E);

    // graph segment ranges
    k_zero_gcnt<<<(GMAX + 255) / 256, 256>>>();
    k_count_g<<<(N + 255) / 256, 256>>>(batch, N);
    k_scan_g<<<1, 1>>>(G);

    const float* bs[3]  = {b1, b2, b3};
    const float* gs[3]  = {g1, g2, g3};
    const float* bes[3] = {be1, be2, be3};
    float* wts[3] = {wt0, wt1, wt2};

    int tc_grid     = (N + 127) / 128;
    int agg_blocks  = (N + 7) / 8;
    int norm_blocks = (N * 32 + 255) / 256;

    const float* xin = x;
    for (int L = 0; L < 3; L++) {
        k_gemm_mma<<<tc_grid, 256, GEMM_SMEM>>>(xin, wts[L], buf1, N, L > 0);
        k_aggregate<<<agg_blocks, 256>>>(buf1, bs[L], buf2, N);
        k_stats_partial<<<P, 128>>>(buf2, N);
        k_stats_final<<<1, 128>>>(P, N, gs[L], bes[L]);
        xin = buf2;   // next GEMM reads raw agg, applies norm+leaky on load
    }

    // materialize normalized layer-3 output for pooling
    k_norm<<<norm_blocks, 256>>>(buf2, buf0, N);

    // pool + final MLP
    k_pool<<<(G + 7) / 8, 256>>>(buf0, G);
    int gemm_blocks_g = (G + 127) / 128;
    k_gemm<<<gemm_blocks_g, 256>>>(pooled, Wf1, bf1, z1, G, 1);
    k_bn_small<<<1, 128>>>(z1, g4, be4, z2, G);
    k_gemm<<<gemm_blocks_g, 256>>>(z2, Wf2, bf2, (float*)d_out, G, 1);
}

// round 4
// speedup vs baseline: 1.0968x; 1.0212x over previous
#include <cuda_runtime.h>
#include <math.h>
#include <stdint.h>

#define D 128
#define NMAX 50000
#define EMAX 800000
#define GMAX 512
#define BN_EPS 1e-5f
#define SLOPE 0.1f
#define CH 512
#define NCMAX 128
#define SROWS 256
#define SPMAX 256

// ---------------- scratch (static device globals; no allocation) -------------
__device__ float g_buf0[NMAX * D];
__device__ float g_buf1[NMAX * D];
__device__ float g_buf2[NMAX * D];
__device__ float g_WT[3][D * D];
__device__ float g_dinv[NMAX];
__device__ int   g_deg[NMAX];
__device__ int   g_rowstart[NMAX + 1];
__device__ int   g_wpos[NMAX];
__device__ int   g_srcs[EMAX];
__device__ float g_ecoef[EMAX];
__device__ int   g_csum[NCMAX];
__device__ int   g_coff[NCMAX];
__device__ float g_psum[SPMAX * D];
__device__ float g_psumsq[SPMAX * D];
__device__ float g_scale[D];
__device__ float g_shift[D];
__device__ int   g_gcnt[GMAX];
__device__ int   g_gstart[GMAX + 1];
__device__ float g_pooled[GMAX * D];
__device__ float g_z1[GMAX * D];
__device__ float g_z2[GMAX * D];

// ---------------- tf32 split helper ------------------------------------------
__device__ __forceinline__ void tf32_split(float v, float& hi, float& lo) {
    uint32_t t;
    asm("cvt.rna.tf32.f32 %0, %1;" : "=r"(t) : "f"(v));
    hi = __uint_as_float(t);
    float r = v - hi;
    asm("cvt.rna.tf32.f32 %0, %1;" : "=r"(t) : "f"(r));
    lo = __uint_as_float(t);
}

__device__ __forceinline__ void mma_tf32(float* d, uint32_t a0, uint32_t a1,
                                         uint32_t a2, uint32_t a3,
                                         uint32_t b0, uint32_t b1) {
    asm volatile(
        "mma.sync.aligned.m16n8k8.row.col.f32.tf32.tf32.f32 "
        "{%0,%1,%2,%3}, {%4,%5,%6,%7}, {%8,%9}, {%0,%1,%2,%3};"
        : "+f"(d[0]), "+f"(d[1]), "+f"(d[2]), "+f"(d[3])
        : "r"(a0), "r"(a1), "r"(a2), "r"(a3), "r"(b0), "r"(b1));
}

// ---------------- mma.sync tf32 3-term split GEMM ----------------------------
#define AST 36
#define GEMM_SMEM (4 * 128 * AST * 4)

__global__ void __launch_bounds__(256, 2)
k_gemm_mma(const float* __restrict__ A, const float* __restrict__ WT,
           float* __restrict__ C, int M, int apply_norm) {
    extern __shared__ float sm[];
    float* sAh = sm;
    float* sAl = sm + 128 * AST;
    float* sBh = sm + 2 * 128 * AST;
    float* sBl = sm + 3 * 128 * AST;

    const int tid = threadIdx.x;
    const int wid = tid >> 5;
    const int lid = tid & 31;
    const int g   = lid >> 2;
    const int tg  = lid & 3;
    const int wm  = wid & 1;
    const int wn  = wid >> 1;
    const int row0 = blockIdx.x * 128;

    float acc[4][4][4];
#pragma unroll
    for (int mt = 0; mt < 4; mt++)
#pragma unroll
        for (int nt = 0; nt < 4; nt++)
#pragma unroll
            for (int i = 0; i < 4; i++) acc[mt][nt][i] = 0.0f;

    for (int p = 0; p < 4; p++) {
        if (p) __syncthreads();
#pragma unroll
        for (int i = 0; i < 4; i++) {
            int idx = tid + i * 256;
            int r = idx >> 3;
            int c = (idx & 7) * 4;
            float4 v = make_float4(0.f, 0.f, 0.f, 0.f);
            if (row0 + r < M)
                v = *(const float4*)&A[(size_t)(row0 + r) * 128 + p * 32 + c];
            if (apply_norm) {
                int cg = p * 32 + c;
                v.x = v.x * g_scale[cg]     + g_shift[cg];
                v.y = v.y * g_scale[cg + 1] + g_shift[cg + 1];
                v.z = v.z * g_scale[cg + 2] + g_shift[cg + 2];
                v.w = v.w * g_scale[cg + 3] + g_shift[cg + 3];
                v.x = v.x > 0.f ? v.x : SLOPE * v.x;
                v.y = v.y > 0.f ? v.y : SLOPE * v.y;
                v.z = v.z > 0.f ? v.z : SLOPE * v.z;
                v.w = v.w > 0.f ? v.w : SLOPE * v.w;
            }
            float4 hi, lo;
            tf32_split(v.x, hi.x, lo.x);
            tf32_split(v.y, hi.y, lo.y);
            tf32_split(v.z, hi.z, lo.z);
            tf32_split(v.w, hi.w, lo.w);
            *(float4*)&sAh[r * AST + c] = hi;
            *(float4*)&sAl[r * AST + c] = lo;
        }
#pragma unroll
        for (int i = 0; i < 4; i++) {
            int idx = tid + i * 256;
            int r = idx >> 3;
            int c = (idx & 7) * 4;
            float4 v = *(const float4*)&WT[(size_t)r * 128 + p * 32 + c];
            float4 hi, lo;
            tf32_split(v.x, hi.x, lo.x);
            tf32_split(v.y, hi.y, lo.y);
            tf32_split(v.z, hi.z, lo.z);
            tf32_split(v.w, hi.w, lo.w);
            *(float4*)&sBh[r * AST + c] = hi;
            *(float4*)&sBl[r * AST + c] = lo;
        }
        __syncthreads();

#pragma unroll
        for (int t = 0; t < 3; t++) {
            const float* As = (t == 2) ? sAl : sAh;
            const float* Bs = (t == 1) ? sBl : sBh;
#pragma unroll
            for (int k8 = 0; k8 < 4; k8++) {
                int k0 = k8 * 8;
                uint32_t af[4][4];
#pragma unroll
                for (int mt = 0; mt < 4; mt++) {
                    int r0 = wm * 64 + mt * 16 + g;
                    af[mt][0] = __float_as_uint(As[r0 * AST + k0 + tg]);
                    af[mt][1] = __float_as_uint(As[(r0 + 8) * AST + k0 + tg]);
                    af[mt][2] = __float_as_uint(As[r0 * AST + k0 + tg + 4]);
                    af[mt][3] = __float_as_uint(As[(r0 + 8) * AST + k0 + tg + 4]);
                }
                uint32_t bf[4][2];
#pragma unroll
                for (int nt = 0; nt < 4; nt++) {
                    int c0 = wn * 32 + nt * 8 + g;
                    bf[nt][0] = __float_as_uint(Bs[c0 * AST + k0 + tg]);
                    bf[nt][1] = __float_as_uint(Bs[c0 * AST + k0 + tg + 4]);
                }
#pragma unroll
                for (int mt = 0; mt < 4; mt++)
#pragma unroll
                    for (int nt = 0; nt < 4; nt++)
                        mma_tf32(acc[mt][nt], af[mt][0], af[mt][1], af[mt][2],
                                 af[mt][3], bf[nt][0], bf[nt][1]);
            }
        }
    }
    __syncthreads();

    float* sOut = sm;
#pragma unroll
    for (int mt = 0; mt < 4; mt++) {
        int r0 = wm * 64 + mt * 16 + g;
#pragma unroll
        for (int nt = 0; nt < 4; nt++) {
            int c0 = wn * 32 + nt * 8 + tg * 2;
            sOut[r0 * 129 + c0]           = acc[mt][nt][0];
            sOut[r0 * 129 + c0 + 1]       = acc[mt][nt][1];
            sOut[(r0 + 8) * 129 + c0]     = acc[mt][nt][2];
            sOut[(r0 + 8) * 129 + c0 + 1] = acc[mt][nt][3];
        }
    }
    __syncthreads();

#pragma unroll 4
    for (int i = 0; i < 64; i++) {
        int idx = tid + i * 256;
        int r = idx >> 7;
        int c = idx & 127;
        if (row0 + r < M)
            C[(size_t)(row0 + r) * 128 + c] = sOut[r * 129 + c];
    }
}

// ---------------- weight transpose (3 layers in one launch) ------------------
__global__ void k_transpose3(const float* __restrict__ W1, const float* __restrict__ W2,
                             const float* __restrict__ W3, float* __restrict__ WT) {
    __shared__ float t[32][33];
    const float* W = (blockIdx.z == 0) ? W1 : (blockIdx.z == 1) ? W2 : W3;
    float* O = WT + blockIdx.z * D * D;
    int bx = blockIdx.x, by = blockIdx.y;
    int tx = threadIdx.x, ty = threadIdx.y;
#pragma unroll
    for (int i = 0; i < 32; i += 8)
        t[ty + i][tx] = W[(by * 32 + ty + i) * 128 + bx * 32 + tx];
    __syncthreads();
#pragma unroll
    for (int i = 0; i < 32; i += 8)
        O[(bx * 32 + ty + i) * 128 + by * 32 + tx] = t[tx][ty + i];
}

// ---------------- init / count / scan ----------------------------------------
__global__ void k_zero(int N) {
    int i = blockIdx.x * blockDim.x + threadIdx.x;
    if (i < N) g_deg[i] = 0;
    if (i < GMAX) g_gcnt[i] = 0;
}
__global__ void k_count(const int* __restrict__ ei, const int* __restrict__ batch,
                        int E, int N) {
    int i = blockIdx.x * blockDim.x + threadIdx.x;
    if (i < E) atomicAdd(&g_deg[ei[E + i]], 1);
    if (i < N) atomicAdd(&g_gcnt[batch[i]], 1);
}
__global__ void k_dinv(int N) {
    int i = blockIdx.x * blockDim.x + threadIdx.x;
    if (i < N) g_dinv[i] = rsqrtf((float)g_deg[i] + 1.0f);
}
__global__ void k_chunksum(int N) {
    __shared__ int s[CH];
    int i = blockIdx.x * CH + threadIdx.x;
    s[threadIdx.x] = (i < N) ? g_deg[i] : 0;
    __syncthreads();
    for (int off = CH / 2; off > 0; off >>= 1) {
        if (threadIdx.x < off) s[threadIdx.x] += s[threadIdx.x + off];
        __syncthreads();
    }
    if (threadIdx.x == 0) g_csum[blockIdx.x] = s[0];
}
// block 0: exclusive scan of chunk sums; block 1: graph ranges scan
__global__ void k_scan2(int NC, int N, int G) {
    if (blockIdx.x == 0) {
        if (threadIdx.x == 0) {
            int run = 0;
            for (int i = 0; i < NC; i++) { g_coff[i] = run; run += g_csum[i]; }
            g_rowstart[N] = run;
        }
    } else {
        if (threadIdx.x == 0) {
            int run = 0;
            for (int i = 0; i < G; i++) { g_gstart[i] = run; run += g_gcnt[i]; }
            g_gstart[G] = run;
        }
    }
}
__global__ void k_chunkscan(int N) {
    __shared__ int s[CH];
    int i = blockIdx.x * CH + threadIdx.x;
    int v = (i < N) ? g_deg[i] : 0;
    s[threadIdx.x] = v;
    __syncthreads();
    for (int off = 1; off < CH; off <<= 1) {
        int t = (threadIdx.x >= off) ? s[threadIdx.x - off] : 0;
        __syncthreads();
        s[threadIdx.x] += t;
        __syncthreads();
    }
    if (i < N) {
        int excl = g_coff[blockIdx.x] + s[threadIdx.x] - v;
        g_rowstart[i] = excl;
        g_wpos[i] = excl;
    }
}
__global__ void k_scatter(const int* __restrict__ ei, int E) {
    int e = blockIdx.x * blockDim.x + threadIdx.x;
    if (e < E) {
        int s = ei[e];
        int d = ei[E + e];
        int p = atomicAdd(&g_wpos[d], 1);
        g_srcs[p] = s;
        g_ecoef[p] = g_dinv[s] * g_dinv[d];
    }
}

// ---------------- edge aggregation: warp/dst, 4-wide MLP ---------------------
__global__ void k_aggregate(const float* __restrict__ h, const float* __restrict__ bias,
                            float* __restrict__ agg, int N) {
    int warp = (blockIdx.x * blockDim.x + threadIdx.x) >> 5;
    int lane = threadIdx.x & 31;
    if (warp >= N) return;
    const float4* __restrict__ h4 = (const float4*)h;
    float di = g_dinv[warp];
    float sc = di * di;
    float4 a = h4[(size_t)warp * 32 + lane];
    float4 acc0, acc1, acc2, acc3;
    acc0.x = a.x * sc; acc0.y = a.y * sc; acc0.z = a.z * sc; acc0.w = a.w * sc;
    acc1 = make_float4(0.f, 0.f, 0.f, 0.f);
    acc2 = make_float4(0.f, 0.f, 0.f, 0.f);
    acc3 = make_float4(0.f, 0.f, 0.f, 0.f);

    int j = g_rowstart[warp];
    int s1 = g_rowstart[warp + 1];
    for (; j + 4 <= s1; j += 4) {
        int i0 = g_srcs[j], i1 = g_srcs[j + 1], i2 = g_srcs[j + 2], i3 = g_srcs[j + 3];
        float c0 = g_ecoef[j], c1 = g_ecoef[j + 1], c2 = g_ecoef[j + 2], c3 = g_ecoef[j + 3];
        float4 v0 = h4[(size_t)i0 * 32 + lane];
        float4 v1 = h4[(size_t)i1 * 32 + lane];
        float4 v2 = h4[(size_t)i2 * 32 + lane];
        float4 v3 = h4[(size_t)i3 * 32 + lane];
        acc0.x += v0.x * c0; acc0.y += v0.y * c0; acc0.z += v0.z * c0; acc0.w += v0.w * c0;
        acc1.x += v1.x * c1; acc1.y += v1.y * c1; acc1.z += v1.z * c1; acc1.w += v1.w * c1;
        acc2.x += v2.x * c2; acc2.y += v2.y * c2; acc2.z += v2.z * c2; acc2.w += v2.w * c2;
        acc3.x += v3.x * c3; acc3.y += v3.y * c3; acc3.z += v3.z * c3; acc3.w += v3.w * c3;
    }
    for (; j < s1; j++) {
        int s = g_srcs[j];
        float c = g_ecoef[j];
        float4 v = h4[(size_t)s * 32 + lane];
        acc0.x += v.x * c; acc0.y += v.y * c; acc0.z += v.z * c; acc0.w += v.w * c;
    }
    float4 b = ((const float4*)bias)[lane];
    acc0.x += acc1.x + acc2.x + acc3.x + b.x;
    acc0.y += acc1.y + acc2.y + acc3.y + b.y;
    acc0.z += acc1.z + acc2.z + acc3.z + b.z;
    acc0.w += acc1.w + acc2.w + acc3.w + b.w;
    ((float4*)agg)[(size_t)warp * 32 + lane] = acc0;
}

// ---------------- BatchNorm stats --------------------------------------------
__global__ void k_stats_partial(const float* __restrict__ X, int N) {
    int c = threadIdx.x;
    int r0 = blockIdx.x * SROWS;
    int r1 = min(N, r0 + SROWS);
    float s = 0.f, s2 = 0.f;
    for (int r = r0; r < r1; r++) {
        float v = X[(size_t)r * 128 + c];
        s += v; s2 += v * v;
    }
    g_psum[blockIdx.x * 128 + c] = s;
    g_psumsq[blockIdx.x * 128 + c] = s2;
}
__global__ void k_stats_final(int P, int N, const float* __restrict__ g,
                              const float* __restrict__ be) {
    int c = threadIdx.x;
    float s = 0.f, s2 = 0.f;
    for (int p = 0; p < P; p++) {
        s += g_psum[p * 128 + c];
        s2 += g_psumsq[p * 128 + c];
    }
    float mu = s / (float)N;
    float var = s2 / (float)N - mu * mu;
    float rinv = rsqrtf(var + BN_EPS);
    float sc = rinv * g[c];
    g_scale[c] = sc;
    g_shift[c] = be[c] - mu * sc;
}

// ---------------- mean pool with fused norm+leaky ----------------------------
__global__ void k_pool(const float* __restrict__ h, int G) {
    int warp = (blockIdx.x * blockDim.x + threadIdx.x) >> 5;
    int lane = threadIdx.x & 31;
    if (warp >= G) return;
    const float4* h4 = (const float4*)h;
    int c = lane * 4;
    float4 sc = *(const float4*)&g_scale[c];
    float4 sh = *(const float4*)&g_shift[c];
    int s0 = g_gstart[warp], s1 = g_gstart[warp + 1];
    float4 acc = make_float4(0.f, 0.f, 0.f, 0.f);
    for (int r = s0; r < s1; r++) {
        float4 v = h4[(size_t)r * 32 + lane];
        float tx = v.x * sc.x + sh.x;
        float ty = v.y * sc.y + sh.y;
        float tz = v.z * sc.z + sh.z;
        float tw = v.w * sc.w + sh.w;
        acc.x += tx > 0.f ? tx : SLOPE * tx;
        acc.y += ty > 0.f ? ty : SLOPE * ty;
        acc.z += tz > 0.f ? tz : SLOPE * tz;
        acc.w += tw > 0.f ? tw : SLOPE * tw;
    }
    int cnt = s1 - s0;
    float inv = 1.0f / (float)(cnt > 0 ? cnt : 1);
    acc.x *= inv; acc.y *= inv; acc.z *= inv; acc.w *= inv;
    ((float4*)g_pooled)[(size_t)warp * 32 + lane] = acc;
}

// ---------------- SIMT GEMM (small FC layers) --------------------------------
__global__ void k_gemm(const float* __restrict__ A, const float* __restrict__ B,
                       const float* __restrict__ bias, float* __restrict__ C,
                       int M, int addbias) {
    __shared__ float As[128][33];
    __shared__ float Bs[32][128];
    const int tid = threadIdx.x;
    const int tx = tid & 15;
    const int ty = tid >> 4;
    const int row0 = blockIdx.x * 128;

    float acc[8][8];
#pragma unroll
    for (int i = 0; i < 8; i++)
#pragma unroll
        for (int j = 0; j < 8; j++) acc[i][j] = 0.0f;

    for (int k0 = 0; k0 < 128; k0 += 32) {
#pragma unroll
        for (int i = 0; i < 4; i++) {
            int e = tid + i * 256;
            int r = e >> 3;
            int c = (e & 7) * 4;
            float4 v = make_float4(0.f, 0.f, 0.f, 0.f);
            if (row0 + r < M)
                v = *(const float4*)&A[(size_t)(row0 + r) * 128 + k0 + c];
            As[r][c] = v.x; As[r][c + 1] = v.y; As[r][c + 2] = v.z; As[r][c + 3] = v.w;
        }
#pragma unroll
        for (int i = 0; i < 4; i++) {
            int e = tid + i * 256;
            int r = e >> 5;
            int c = (e & 31) * 4;
            float4 v = *(const float4*)&B[(size_t)(k0 + r) * 128 + c];
            *(float4*)&Bs[r][c] = v;
        }
        __syncthreads();
#pragma unroll
        for (int k = 0; k < 32; k++) {
            float a[8], b[8];
#pragma unroll
            for (int ii = 0; ii < 4; ii++) {
                a[ii]     = As[ty * 4 + ii][k];
                a[4 + ii] = As[64 + ty * 4 + ii][k];
            }
            float4 b0 = *(const float4*)&Bs[k][tx * 4];
            float4 b1 = *(const float4*)&Bs[k][64 + tx * 4];
            b[0] = b0.x; b[1] = b0.y; b[2] = b0.z; b[3] = b0.w;
            b[4] = b1.x; b[5] = b1.y; b[6] = b1.z; b[7] = b1.w;
#pragma unroll
            for (int ii = 0; ii < 8; ii++)
#pragma unroll
                for (int jj = 0; jj < 8; jj++)
                    acc[ii][jj] += a[ii] * b[jj];
        }
        __syncthreads();
    }

#pragma unroll
    for (int ii = 0; ii < 8; ii++) {
        int r = row0 + ((ii < 4) ? (ty * 4 + ii) : (64 + ty * 4 + (ii - 4)));
        if (r < M) {
#pragma unroll
            for (int jg = 0; jg < 2; jg++) {
                int c0 = jg * 64 + tx * 4;
                float4 o;
                o.x = acc[ii][jg * 4 + 0];
                o.y = acc[ii][jg * 4 + 1];
                o.z = acc[ii][jg * 4 + 2];
                o.w = acc[ii][jg * 4 + 3];
                if (addbias) {
                    o.x += bias[c0];     o.y += bias[c0 + 1];
                    o.z += bias[c0 + 2]; o.w += bias[c0 + 3];
                }
                *(float4*)&C[(size_t)r * 128 + c0] = o;
            }
        }
    }
}

// ---------------- small BN + leaky over G rows -------------------------------
__global__ void k_bn_small(const float* __restrict__ z, const float* __restrict__ g4,
                           const float* __restrict__ be4, float* __restrict__ out, int G) {
    int c = threadIdx.x;
    float s = 0.f, s2 = 0.f;
    for (int r = 0; r < G; r++) {
        float v = z[(size_t)r * 128 + c];
        s += v; s2 += v * v;
    }
    float mu = s / (float)G;
    float var = s2 / (float)G - mu * mu;
    float rinv = rsqrtf(var + BN_EPS);
    float gg = g4[c], bb = be4[c];
    for (int r = 0; r < G; r++) {
        float v = z[(size_t)r * 128 + c];
        float t = (v - mu) * rinv * gg + bb;
        out[(size_t)r * 128 + c] = t > 0.f ? t : SLOPE * t;
    }
}

// ---------------- driver ------------------------------------------------------
extern "C" void kernel_launch(void* const* d_in, const int* in_sizes, int n_in,
                              void* d_out, int out_size) {
    const float* x      = (const float*)d_in[0];
    const int*   ei     = (const int*)d_in[1];
    const int*   batch  = (const int*)d_in[2];
    const float* W1  = (const float*)d_in[4];
    const float* b1  = (const float*)d_in[5];
    const float* g1  = (const float*)d_in[6];
    const float* be1 = (const float*)d_in[7];
    const float* W2  = (const float*)d_in[8];
    const float* b2  = (const float*)d_in[9];
    const float* g2  = (const float*)d_in[10];
    const float* be2 = (const float*)d_in[11];
    const float* W3  = (const float*)d_in[12];
    const float* b3  = (const float*)d_in[13];
    const float* g3  = (const float*)d_in[14];
    const float* be3 = (const float*)d_in[15];
    const float* Wf1 = (const float*)d_in[16];
    const float* bf1 = (const float*)d_in[17];
    const float* g4  = (const float*)d_in[18];
    const float* be4 = (const float*)d_in[19];
    const float* Wf2 = (const float*)d_in[20];
    const float* bf2 = (const float*)d_in[21];

    int N = in_sizes[0] / D;
    int E = in_sizes[1] / 2;
    int G = out_size / D;
    if (N > NMAX || E > EMAX || G > GMAX) return;

    cudaFuncSetAttribute(k_gemm_mma, cudaFuncAttributeMaxDynamicSharedMemorySize, GEMM_SMEM);

    float *buf0, *buf1, *buf2, *pooled, *z1, *z2, *wt;
    cudaGetSymbolAddress((void**)&buf0, g_buf0);
    cudaGetSymbolAddress((void**)&buf1, g_buf1);
    cudaGetSymbolAddress((void**)&buf2, g_buf2);
    cudaGetSymbolAddress((void**)&pooled, g_pooled);
    cudaGetSymbolAddress((void**)&z1, g_z1);
    cudaGetSymbolAddress((void**)&z2, g_z2);
    cudaGetSymbolAddress((void**)&wt, g_WT);

    int NC = (N + CH - 1) / CH;
    int P  = (N + SROWS - 1) / SROWS;
    int mx = max(E, N);

    k_transpose3<<<dim3(4, 4, 3), dim3(32, 8)>>>(W1, W2, W3, wt);

    // CSR + graph ranges
    k_zero<<<(N + 255) / 256, 256>>>(N);
    k_count<<<(mx + 255) / 256, 256>>>(ei, batch, E, N);
    k_dinv<<<(N + 255) / 256, 256>>>(N);
    k_chunksum<<<NC, CH>>>(N);
    k_scan2<<<2, 32>>>(NC, N, G);
    k_chunkscan<<<NC, CH>>>(N);
    k_scatter<<<(E + 255) / 256, 256>>>(ei, E);

    const float* bs[3]  = {b1, b2, b3};
    const float* gs[3]  = {g1, g2, g3};
    const float* bes[3] = {be1, be2, be3};

    int tc_grid     = (N + 127) / 128;
    int agg_blocks  = (N + 7) / 8;

    const float* xin = x;
    for (int L = 0; L < 3; L++) {
        k_gemm_mma<<<tc_grid, 256, GEMM_SMEM>>>(xin, wt + L * D * D, buf1, N, L > 0);
        k_aggregate<<<agg_blocks, 256>>>(buf1, bs[L], buf2, N);
        k_stats_partial<<<P, 128>>>(buf2, N);
        k_stats_final<<<1, 128>>>(P, N, gs[L], bes[L]);
        xin = buf2;
    }

    // pool applies final norm+leaky inline
    k_pool<<<(G + 7) / 8, 256>>>(buf2, G);
    int gemm_blocks_g = (G + 127) / 128;
    k_gemm<<<gemm_blocks_g, 256>>>(pooled, Wf1, bf1, z1, G, 1);
    k_bn_small<<<1, 128>>>(z1, g4, be4, z2, G);
    k_gemm<<<gemm_blocks_g, 256>>>(z2, Wf2, bf2, (float*)d_out, G, 1);
}